// round 7
// baseline (speedup 1.0000x reference)
#include <cuda_runtime.h>
#include <cuda_fp16.h>
#include <cstdint>
#include <math.h>

// LayerGate as one GEMM D[65536,512] = X[65536,512] @ W_aug[512,512] (per j-block),
// fp16 single-pass mma.sync.m16n8k16 (fp32 acc), fused gate epilogue.
// A is loaded fp32 from the ORIGINAL inputs (LDG prefetch -> cvt -> STS), so the
// activation prep kernel is gone; its traffic hides under the HMMA issue bound.
// Weight columns reordered n' = h*4 + g so a 128-col CTA tile holds all 4 gate groups.

namespace {
constexpr int STAGE_BYTES = 32768;   // per stage: A 16KB (fp16) + B 16KB
constexpr int SMEM_TOTAL  = 65536;   // 2 stages (reused as 128x128 fp32 gate tile)
}

// [j][n'][k] fp16, n'=512 reordered cols = 2MB
__device__ __align__(16) unsigned char g_wh[4ull * 512 * 1024];

// ---------- PTX helpers (compute_80-level; safe under .target sm_103) ----------
__device__ __forceinline__ uint32_t smem_u32(const void* p) {
    uint32_t a;
    asm("{ .reg .u64 t; cvta.to.shared.u64 t, %1; cvt.u32.u64 %0, t; }" : "=r"(a) : "l"(p));
    return a;
}
__device__ __forceinline__ void cp16(uint32_t dst, const void* src) {
    asm volatile("cp.async.cg.shared.global [%0], [%1], 16;" :: "r"(dst), "l"(src));
}
__device__ __forceinline__ void cp_commit() {
    asm volatile("cp.async.commit_group;" ::: "memory");
}
__device__ __forceinline__ void cp_wait0() {
    asm volatile("cp.async.wait_group 0;" ::: "memory");
}
__device__ __forceinline__ void ldsm4(uint32_t* r, uint32_t addr) {
    asm volatile("ldmatrix.sync.aligned.m8n8.x4.shared.b16 {%0,%1,%2,%3}, [%4];"
                 : "=r"(r[0]), "=r"(r[1]), "=r"(r[2]), "=r"(r[3]) : "r"(addr));
}
__device__ __forceinline__ void mma_fp16(float* d, const uint32_t* a, const uint32_t* b) {
    asm volatile("mma.sync.aligned.m16n8k16.row.col.f32.f16.f16.f32 "
                 "{%0,%1,%2,%3}, {%4,%5,%6,%7}, {%8,%9}, {%0,%1,%2,%3};"
                 : "+f"(d[0]), "+f"(d[1]), "+f"(d[2]), "+f"(d[3])
                 : "r"(a[0]), "r"(a[1]), "r"(a[2]), "r"(a[3]), "r"(b[0]), "r"(b[1]));
}

// ---------- Prep: weights -> fp16 plane, columns reordered n' = h*4+g ----------
__global__ void __launch_bounds__(256) wprep_w(const float* __restrict__ Wcat,
                                               const float* __restrict__ Wexp)
{
    int idx = blockIdx.x * 256 + threadIdx.x;   // 262,144 threads
    int h = idx & 127;
    int k = (idx >> 7) & 511;
    int j = idx >> 16;
#pragma unroll
    for (int g = 0; g < 4; g++) {
        float v;
        if (k < 384)     v = Wcat[(size_t)k * 2048 + j * 512 + g * 128 + h];
        else if (g >= 1) v = Wexp[(size_t)(k - 384) * 1536 + j * 384 + (g - 1) * 128 + h];
        else             v = 0.f;
        int npr = h * 4 + g;
        *reinterpret_cast<__half*>(g_wh + ((size_t)(j * 512) + npr) * 1024 + k * 2) =
            __float2half_rn(v);
    }
}

// ---------- Main: pipelined fp16 HMMA GEMM + in-kernel A conversion + fused epilogue ----------
__global__ void __launch_bounds__(256, 1)
layergate_mma(const float* __restrict__ cnn,
              const float* __restrict__ gaz,
              const float* __restrict__ gazb,
              const float* __restrict__ gm,
              const float* __restrict__ expi,
              const float* __restrict__ bcat,
              const float* __restrict__ bexp,
              float* __restrict__ out)
{
    extern __shared__ __align__(1024) unsigned char smem[];
    const uint32_t sbase = smem_u32(smem);
    const int tid  = threadIdx.x;
    const int lane = tid & 31;
    const int wid  = tid >> 5;
    const int wm   = wid & 3;     // 4 warps in M
    const int wn   = wid >> 2;    // 2 warps in N
    const int nt   = blockIdx.x;  // 0..3   (h-block of 32) — fastest => A rows L2-shared
    const int mx   = blockIdx.y;  // 0..127 (row tile within j)
    const int j    = blockIdx.z;  // 0..3
    const int rbase = j * 16384 + mx * 128;
    const int b    = mx >> 2;           // batch of this 128-row tile
    const int s0   = (mx & 3) * 128;    // sequence offset of row 0

    // Per-sel fp32 row pointers (row stride = 128 floats)
    const float* srcSel[4];
    srcSel[0] = cnn  + ((size_t)(b * 2048 + j * 512 + s0) << 7);
    srcSel[1] = ((j & 1) ? gazb : gaz) + ((size_t)(b * 512 + s0) << 7);
    srcSel[2] = gm   + ((size_t)(b * 512 + s0) << 7);
    srcSel[3] = expi + ((size_t)(b * 512 + s0) << 7);

    float acc[2][8][4];
#pragma unroll
    for (int mf = 0; mf < 2; mf++)
#pragma unroll
        for (int nf = 0; nf < 8; nf++)
#pragma unroll
            for (int c = 0; c < 4; c++) acc[mf][nf][c] = 0.f;

    float4 apre[8];   // A fp32 prefetch: 8 x float4 = one stage (128 rows x 64 k)/256 thr

    // chunk geometry for A: c = i*256+tid, row = c>>4, ch = c&15 (k4 = ch*4)
    auto ldgA = [&](int s) {
        const int sel   = s >> 1;
        const int koff0 = (s & 1) * 64;
        const float* base = srcSel[sel];
#pragma unroll
        for (int i = 0; i < 8; i++) {
            int c = i * 256 + tid;
            int r = c >> 4, ch = c & 15;
            apre[i] = *reinterpret_cast<const float4*>(base + ((size_t)r << 7) + koff0 + ch * 4);
        }
    };
    auto cvtstsA = [&](int s) {
        const uint32_t dst = sbase + (s & 1) * STAGE_BYTES;
#pragma unroll
        for (int i = 0; i < 8; i++) {
            int c = i * 256 + tid;
            int r = c >> 4, ch = c & 15;
            __half2 h0 = __floats2half2_rn(apre[i].x, apre[i].y);
            __half2 h1 = __floats2half2_rn(apre[i].z, apre[i].w);
            uint32_t sw16 = (uint32_t)((ch >> 1) ^ (r & 7));
            uint32_t off  = (uint32_t)r * 128u + sw16 * 16u + (uint32_t)(ch & 1) * 8u;
            uint2 v = make_uint2(*reinterpret_cast<uint32_t*>(&h0),
                                 *reinterpret_cast<uint32_t*>(&h1));
            *reinterpret_cast<uint2*>(smem + (s & 1) * STAGE_BYTES + off) = v;
            (void)dst;
        }
    };
    auto issueB = [&](int s) {
        const uint32_t dstStage = sbase + (s & 1) * STAGE_BYTES + 16384;
#pragma unroll
        for (int i = 0; i < 4; i++) {
            int c = i * 256 + tid;                 // 1024 B chunks
            int r = c >> 3, ch = c & 7;
            const unsigned char* src =
                g_wh + ((size_t)(j * 512) + nt * 128 + r) * 1024 + s * 128 + ch * 16;
            cp16(dstStage + r * 128 + ((ch ^ (r & 7)) * 16), src);
        }
        cp_commit();
    };

    // ldmatrix lane geometry
    const int arow = lane & 15;
    const int ac   = lane >> 4;
    const int brow = (lane & 7) | ((lane >> 4) << 3);
    const int bc   = (lane >> 3) & 1;

    auto compute_stage = [&](int s) {
        const uint32_t st = sbase + (s & 1) * STAGE_BYTES;
        const uint32_t aBase = st + (wm * 32 + arow) * 128;
        const uint32_t bBase = st + 16384 + (wn * 64 + brow) * 128;
#pragma unroll
        for (int kk = 0; kk < 4; kk++) {
            const uint32_t aoff = ((kk * 2 + ac) ^ (arow & 7)) * 16;
            const uint32_t boff = ((kk * 2 + bc) ^ (brow & 7)) * 16;
            uint32_t A[2][4];
#pragma unroll
            for (int mf = 0; mf < 2; mf++) ldsm4(A[mf], aBase + mf * 2048 + aoff);
            uint32_t B[8][2];
#pragma unroll
            for (int ng = 0; ng < 4; ng++) {
                uint32_t t[4];
                ldsm4(t, bBase + ng * 2048 + boff);
                B[2 * ng][0] = t[0]; B[2 * ng][1] = t[1];
                B[2 * ng + 1][0] = t[2]; B[2 * ng + 1][1] = t[3];
            }
#pragma unroll
            for (int mf = 0; mf < 2; mf++)
#pragma unroll
                for (int nf = 0; nf < 8; nf++)
                    mma_fp16(acc[mf][nf], A[mf], B[nf]);
        }
    };

    ldgA(0);
    issueB(0);
    for (int s = 0; s < 8; s++) {
        cvtstsA(s);                   // consume apre into stage buf s&1
        if (s < 7) ldgA(s + 1);       // refill apre; latency hides under compute(s)
        cp_wait0();                   // B(s) arrived
        __syncthreads();              // A STS visible + prev-stage buffers free
        if (s < 7) issueB(s + 1);
        compute_stage(s);
    }

    // ---- Epilogue phase 1: dump acc to smem gate tile [128 rows][128 n'] fp32
    __syncthreads();
    float* gate = reinterpret_cast<float*>(smem);
    const int gid = lane >> 2, tig = lane & 3;
#pragma unroll
    for (int mf = 0; mf < 2; mf++)
#pragma unroll
        for (int nf = 0; nf < 8; nf++) {
            int row = wm * 32 + mf * 16 + gid;
            int col = wn * 64 + nf * 8 + tig * 2;
            *reinterpret_cast<float2*>(gate + row * 128 + col) =
                make_float2(acc[mf][nf][0], acc[mf][nf][1]);
            *reinterpret_cast<float2*>(gate + (row + 8) * 128 + col) =
                make_float2(acc[mf][nf][2], acc[mf][nf][3]);
        }
    __syncthreads();

    // ---- Epilogue phase 2: per (row, h) gather float4 {ns,g1,g2,g3}, finish, store
    const int hl = lane;
    const int hg = nt * 32 + hl;
    const float bc0 = bcat[j * 512 + hg];
    const float bc1 = bcat[j * 512 + 128 + hg];
    const float bc2 = bcat[j * 512 + 256 + hg];
    const float bc3 = bcat[j * 512 + 384 + hg];
    const float be1 = bexp[j * 384 + hg];
    const float be2 = bexp[j * 384 + 128 + hg];
    const float be3 = bexp[j * 384 + 256 + hg];
#pragma unroll
    for (int i = 0; i < 16; i++) {
        const int row = wid * 16 + i;
        const int r = rbase + row;
        float4 gv = *reinterpret_cast<const float4*>(gate + row * 128 + hl * 4);
        float s1 = srcSel[0][((size_t)row << 7) + hg];
        float s2 = srcSel[3][((size_t)row << 7) + hg];
        float ns = tanhf(gv.x + bc0);
        float g1 = 1.f / (1.f + __expf(-(gv.y + bc1 + be1)));
        float g2 = 1.f / (1.f + __expf(-(gv.z + bc2 + be2)));
        float g3 = 1.f / (1.f + __expf(-(gv.w + bc3 + be3)));
        float e1 = __expf(g1), e2 = __expf(g2), e3 = __expf(g3);
        float inv = 1.f / (e1 + e2 + e3);
        out[((size_t)r << 7) + hg] = (e1 * ns + e2 * s1 + e3 * s2) * inv;
    }
}

extern "C" void kernel_launch(void* const* d_in, const int* in_sizes, int n_in,
                              void* d_out, int out_size)
{
    const float* cnn  = (const float*)d_in[0];
    const float* gaz  = (const float*)d_in[1];
    const float* gazb = (const float*)d_in[2];
    const float* gm   = (const float*)d_in[3];
    const float* expi = (const float*)d_in[4];
    const float* Wcat = (const float*)d_in[5];
    const float* bcat = (const float*)d_in[6];
    const float* Wexp = (const float*)d_in[7];
    const float* bexp = (const float*)d_in[8];
    float* out = (float*)d_out;

    wprep_w<<<1024, 256>>>(Wcat, Wexp);

    cudaFuncSetAttribute(layergate_mma,
                         cudaFuncAttributeMaxDynamicSharedMemorySize, SMEM_TOTAL);
    layergate_mma<<<dim3(4, 128, 4), 256, SMEM_TOTAL>>>(
        cnn, gaz, gazb, gm, expi, bcat, bexp, out);
}

// round 9
// speedup vs baseline: 1.1642x; 1.1642x over previous
#include <cuda_runtime.h>
#include <cuda_fp16.h>
#include <cstdint>
#include <math.h>

// LayerGate as one GEMM D[65536,512] = X[65536,512] @ W_aug[512,512] (per j-block),
// fp16 single-pass mma.sync.m16n8k16 (fp32 acc), fused gate epilogue.
// 4-stage cp.async pipeline (K-slice 32, 16KB/stage), 2 CTAs/SM.
// Weight columns reordered n' = h*4 + g so a 128-col CTA tile holds all 4 gate groups.

namespace {
constexpr int STAGE_BYTES = 16384;   // per stage: A 8KB + B 8KB (K=32 slice)
constexpr int NSTAGE      = 4;
constexpr int SMEM_TOTAL  = 65536;   // 4 stages (reused as 128x128 fp32 gate tile)
}

// [r][k] fp16, 65536 rows x 512 k = 64MB (fits L2)
__device__ __align__(16) unsigned char g_ah[65536ull * 1024];
// [j][n'][k] fp16, n'=512 reordered cols = 2MB
__device__ __align__(16) unsigned char g_wh[4ull * 512 * 1024];

// ---------- PTX helpers (compute_80-level; safe under .target sm_103) ----------
__device__ __forceinline__ uint32_t smem_u32(const void* p) {
    uint32_t a;
    asm("{ .reg .u64 t; cvta.to.shared.u64 t, %1; cvt.u32.u64 %0, t; }" : "=r"(a) : "l"(p));
    return a;
}
__device__ __forceinline__ void cp16(uint32_t dst, const void* src) {
    asm volatile("cp.async.cg.shared.global [%0], [%1], 16;" :: "r"(dst), "l"(src));
}
__device__ __forceinline__ void cp_commit() {
    asm volatile("cp.async.commit_group;" ::: "memory");
}
__device__ __forceinline__ void cp_wait2() {
    asm volatile("cp.async.wait_group 2;" ::: "memory");
}
__device__ __forceinline__ void ldsm4(uint32_t* r, uint32_t addr) {
    asm volatile("ldmatrix.sync.aligned.m8n8.x4.shared.b16 {%0,%1,%2,%3}, [%4];"
                 : "=r"(r[0]), "=r"(r[1]), "=r"(r[2]), "=r"(r[3]) : "r"(addr));
}
__device__ __forceinline__ void mma_fp16(float* d, const uint32_t* a, const uint32_t* b) {
    asm volatile("mma.sync.aligned.m16n8k16.row.col.f32.f16.f16.f32 "
                 "{%0,%1,%2,%3}, {%4,%5,%6,%7}, {%8,%9}, {%0,%1,%2,%3};"
                 : "+f"(d[0]), "+f"(d[1]), "+f"(d[2]), "+f"(d[3])
                 : "r"(a[0]), "r"(a[1]), "r"(a[2]), "r"(a[3]), "r"(b[0]), "r"(b[1]));
}

// ---------- Prep: activations -> fp16 plane [r][k] ----------
__global__ void __launch_bounds__(256) wprep_a(const float* __restrict__ cnn,
                                               const float* __restrict__ gaz,
                                               const float* __restrict__ gazb,
                                               const float* __restrict__ gm,
                                               const float* __restrict__ expi)
{
    int idx = blockIdx.x * 256 + threadIdx.x;   // 8,388,608 threads
    int k4  = idx & 127;                        // k = k4*4
    int r   = idx >> 7;
    int j = r >> 14, b = (r >> 9) & 31, s = r & 511;
    int k = k4 * 4;
    int sel = k >> 7;
    const float* rp;
    if (sel == 0)      rp = cnn  + ((size_t)(b * 2048 + j * 512 + s) << 7);
    else if (sel == 1) rp = ((j & 1) ? gazb : gaz) + ((size_t)(b * 512 + s) << 7);
    else if (sel == 2) rp = gm   + ((size_t)(b * 512 + s) << 7);
    else               rp = expi + ((size_t)(b * 512 + s) << 7);
    float4 v = *reinterpret_cast<const float4*>(rp + (k & 127));
    __half2 h0 = __floats2half2_rn(v.x, v.y);
    __half2 h1 = __floats2half2_rn(v.z, v.w);
    *reinterpret_cast<uint2*>(g_ah + (size_t)r * 1024 + k4 * 8) =
        make_uint2(*reinterpret_cast<uint32_t*>(&h0), *reinterpret_cast<uint32_t*>(&h1));
}

// ---------- Prep: weights -> fp16 plane, columns reordered n' = h*4+g ----------
__global__ void __launch_bounds__(256) wprep_w(const float* __restrict__ Wcat,
                                               const float* __restrict__ Wexp)
{
    int idx = blockIdx.x * 256 + threadIdx.x;   // 262,144 threads
    int h = idx & 127;
    int k = (idx >> 7) & 511;
    int j = idx >> 16;
#pragma unroll
    for (int g = 0; g < 4; g++) {
        float v;
        if (k < 384)     v = Wcat[(size_t)k * 2048 + j * 512 + g * 128 + h];
        else if (g >= 1) v = Wexp[(size_t)(k - 384) * 1536 + j * 384 + (g - 1) * 128 + h];
        else             v = 0.f;
        int npr = h * 4 + g;
        *reinterpret_cast<__half*>(g_wh + ((size_t)(j * 512) + npr) * 1024 + k * 2) =
            __float2half_rn(v);
    }
}

// ---------- Main: 4-stage pipelined fp16 HMMA GEMM + fused epilogue ----------
__global__ void __launch_bounds__(256, 2)
layergate_mma(const float* __restrict__ cnn,
              const float* __restrict__ expi,
              const float* __restrict__ bcat,
              const float* __restrict__ bexp,
              float* __restrict__ out)
{
    extern __shared__ __align__(1024) unsigned char smem[];
    const uint32_t sbase = smem_u32(smem);
    const int tid  = threadIdx.x;
    const int lane = tid & 31;
    const int wid  = tid >> 5;
    const int wm   = wid & 3;     // 4 warps in M
    const int wn   = wid >> 2;    // 2 warps in N
    const int nt   = blockIdx.x;  // 0..3   (h-block of 32) — fastest => A rows L2-shared
    const int mx   = blockIdx.y;  // 0..127 (row tile within j)
    const int j    = blockIdx.z;  // 0..3
    const int rbase = j * 16384 + mx * 128;

    float acc[2][8][4];
#pragma unroll
    for (int mf = 0; mf < 2; mf++)
#pragma unroll
        for (int nf = 0; nf < 8; nf++)
#pragma unroll
            for (int c = 0; c < 4; c++) acc[mf][nf][c] = 0.f;

    // ---- cp.async stage loader: 4 x 16B per thread (A 8KB + B 8KB), K-slice = 32
    // 64B rows; swizzle chunk' = ch ^ ((r>>1)&3) -> conflict-free ldmatrix
    auto issue_stage = [&](int s) {
        const uint32_t dstStage = sbase + (s & (NSTAGE - 1)) * STAGE_BYTES;
#pragma unroll
        for (int i = 0; i < 2; i++) {
            int c = i * 256 + tid;                 // 512 A chunks
            int r = c >> 2, ch = c & 3;
            const unsigned char* src =
                g_ah + (size_t)(rbase + r) * 1024 + s * 64 + ch * 16;
            cp16(dstStage + r * 64 + ((ch ^ ((r >> 1) & 3)) * 16), src);
        }
#pragma unroll
        for (int i = 0; i < 2; i++) {
            int c = i * 256 + tid;                 // 512 B chunks
            int r = c >> 2, ch = c & 3;
            const unsigned char* src =
                g_wh + ((size_t)(j * 512) + nt * 128 + r) * 1024 + s * 64 + ch * 16;
            cp16(dstStage + 8192 + r * 64 + ((ch ^ ((r >> 1) & 3)) * 16), src);
        }
        cp_commit();
    };

    // ldmatrix lane geometry
    const int arow = lane & 15;
    const int ac   = lane >> 4;
    const int brow = (lane & 7) | ((lane >> 4) << 3);
    const int bc   = (lane >> 3) & 1;

    auto compute_stage = [&](int s) {
        const uint32_t st = sbase + (s & (NSTAGE - 1)) * STAGE_BYTES;
        const uint32_t aBase = st + (wm * 32 + arow) * 64;
        const uint32_t bBase = st + 8192 + (wn * 64 + brow) * 64;
        const uint32_t asw = (uint32_t)((arow >> 1) & 3);
        const uint32_t bsw = (uint32_t)((brow >> 1) & 3);
#pragma unroll
        for (int kk = 0; kk < 2; kk++) {
            const uint32_t aoff = (((uint32_t)(kk * 2 + ac)) ^ asw) * 16;
            const uint32_t boff = (((uint32_t)(kk * 2 + bc)) ^ bsw) * 16;
            uint32_t A[2][4];
#pragma unroll
            for (int mf = 0; mf < 2; mf++) ldsm4(A[mf], aBase + mf * 1024 + aoff);
            uint32_t B[8][2];
#pragma unroll
            for (int ng = 0; ng < 4; ng++) {
                uint32_t t[4];
                ldsm4(t, bBase + ng * 1024 + boff);
                B[2 * ng][0] = t[0]; B[2 * ng][1] = t[1];
                B[2 * ng + 1][0] = t[2]; B[2 * ng + 1][1] = t[3];
            }
#pragma unroll
            for (int mf = 0; mf < 2; mf++)
#pragma unroll
                for (int nf = 0; nf < 8; nf++)
                    mma_fp16(acc[mf][nf], A[mf], B[nf]);
        }
    };

    issue_stage(0);
    issue_stage(1);
    issue_stage(2);
    for (int s = 0; s < 16; s++) {
        cp_wait2();                      // stage s landed (2 stages still in flight)
        __syncthreads();
        if (s + 3 < 16) issue_stage(s + 3);
        else            cp_commit();     // empty group keeps wait arithmetic exact
        compute_stage(s);
    }

    // ---- Epilogue phase 1: dump acc to smem gate tile [128 rows][128 n'] fp32
    __syncthreads();
    float* gate = reinterpret_cast<float*>(smem);
    const int gid = lane >> 2, tig = lane & 3;
#pragma unroll
    for (int mf = 0; mf < 2; mf++)
#pragma unroll
        for (int nf = 0; nf < 8; nf++) {
            int row = wm * 32 + mf * 16 + gid;
            int col = wn * 64 + nf * 8 + tig * 2;
            *reinterpret_cast<float2*>(gate + row * 128 + col) =
                make_float2(acc[mf][nf][0], acc[mf][nf][1]);
            *reinterpret_cast<float2*>(gate + (row + 8) * 128 + col) =
                make_float2(acc[mf][nf][2], acc[mf][nf][3]);
        }
    __syncthreads();

    // ---- Epilogue phase 2: per (row, h) gather float4 {ns,g1,g2,g3}, finish, store
    const int hl = lane;
    const int hg = nt * 32 + hl;
    const float bc0 = bcat[j * 512 + hg];
    const float bc1 = bcat[j * 512 + 128 + hg];
    const float bc2 = bcat[j * 512 + 256 + hg];
    const float bc3 = bcat[j * 512 + 384 + hg];
    const float be1 = bexp[j * 384 + hg];
    const float be2 = bexp[j * 384 + 128 + hg];
    const float be3 = bexp[j * 384 + 256 + hg];
#pragma unroll
    for (int i = 0; i < 16; i++) {
        const int row = wid * 16 + i;
        const int r = rbase + row;
        const int bb = (r >> 9) & 31, ss = r & 511;
        float4 gv = *reinterpret_cast<const float4*>(gate + row * 128 + hl * 4);
        float s1 = cnn[((size_t)(bb * 2048 + j * 512 + ss) << 7) + hg];
        float s2 = expi[((size_t)(bb * 512 + ss) << 7) + hg];
        float ns = tanhf(gv.x + bc0);
        float g1 = 1.f / (1.f + __expf(-(gv.y + bc1 + be1)));
        float g2 = 1.f / (1.f + __expf(-(gv.z + bc2 + be2)));
        float g3 = 1.f / (1.f + __expf(-(gv.w + bc3 + be3)));
        float e1 = __expf(g1), e2 = __expf(g2), e3 = __expf(g3);
        float inv = 1.f / (e1 + e2 + e3);
        out[((size_t)r << 7) + hg] = (e1 * ns + e2 * s1 + e3 * s2) * inv;
    }
}

extern "C" void kernel_launch(void* const* d_in, const int* in_sizes, int n_in,
                              void* d_out, int out_size)
{
    const float* cnn  = (const float*)d_in[0];
    const float* gaz  = (const float*)d_in[1];
    const float* gazb = (const float*)d_in[2];
    const float* gm   = (const float*)d_in[3];
    const float* expi = (const float*)d_in[4];
    const float* Wcat = (const float*)d_in[5];
    const float* bcat = (const float*)d_in[6];
    const float* Wexp = (const float*)d_in[7];
    const float* bexp = (const float*)d_in[8];
    float* out = (float*)d_out;

    wprep_a<<<32768, 256>>>(cnn, gaz, gazb, gm, expi);
    wprep_w<<<1024, 256>>>(Wcat, Wexp);

    cudaFuncSetAttribute(layergate_mma,
                         cudaFuncAttributeMaxDynamicSharedMemorySize, SMEM_TOTAL);
    layergate_mma<<<dim3(4, 128, 4), 256, SMEM_TOTAL>>>(cnn, expi, bcat, bexp, out);
}

// round 12
// speedup vs baseline: 1.2167x; 1.0451x over previous
#include <cuda_runtime.h>
#include <cuda_fp16.h>
#include <cstdint>
#include <math.h>

// LayerGate as one GEMM D[65536,512] = X[65536,512] @ W_aug[512,512] (per j-block),
// fp16 single-pass mma.sync.m16n8k16 (fp32 acc), fused gate epilogue.
// 3-stage cp.async pipeline (K-slice 64, 32KB/stage, wait_group 1), 2 CTAs/SM.
// Weight columns reordered n' = h*4 + g so a 128-col CTA tile holds all 4 gate groups.

namespace {
constexpr int STAGE_BYTES = 32768;   // per stage: A 16KB + B 16KB (K=64 slice)
constexpr int NSTAGE      = 3;
constexpr int SMEM_TOTAL  = 98304;   // 3 stages (front 64KB reused as 128x128 fp32 gate tile)
}

// [r][k] fp16, 65536 rows x 512 k = 64MB (fits L2)
__device__ __align__(16) unsigned char g_ah[65536ull * 1024];
// [j][n'][k] fp16, n'=512 reordered cols = 2MB
__device__ __align__(16) unsigned char g_wh[4ull * 512 * 1024];

// ---------- PTX helpers (compute_80-level; safe under .target sm_103) ----------
__device__ __forceinline__ uint32_t smem_u32(const void* p) {
    uint32_t a;
    asm("{ .reg .u64 t; cvta.to.shared.u64 t, %1; cvt.u32.u64 %0, t; }" : "=r"(a) : "l"(p));
    return a;
}
__device__ __forceinline__ void cp16(uint32_t dst, const void* src) {
    asm volatile("cp.async.cg.shared.global [%0], [%1], 16;" :: "r"(dst), "l"(src));
}
__device__ __forceinline__ void cp_commit() {
    asm volatile("cp.async.commit_group;" ::: "memory");
}
__device__ __forceinline__ void cp_wait1() {
    asm volatile("cp.async.wait_group 1;" ::: "memory");
}
__device__ __forceinline__ void ldsm4(uint32_t* r, uint32_t addr) {
    asm volatile("ldmatrix.sync.aligned.m8n8.x4.shared.b16 {%0,%1,%2,%3}, [%4];"
                 : "=r"(r[0]), "=r"(r[1]), "=r"(r[2]), "=r"(r[3]) : "r"(addr));
}
__device__ __forceinline__ void mma_fp16(float* d, const uint32_t* a, const uint32_t* b) {
    asm volatile("mma.sync.aligned.m16n8k16.row.col.f32.f16.f16.f32 "
                 "{%0,%1,%2,%3}, {%4,%5,%6,%7}, {%8,%9}, {%0,%1,%2,%3};"
                 : "+f"(d[0]), "+f"(d[1]), "+f"(d[2]), "+f"(d[3])
                 : "r"(a[0]), "r"(a[1]), "r"(a[2]), "r"(a[3]), "r"(b[0]), "r"(b[1]));
}

// ---------- Merged prep: activations + weights -> fp16 planes (one launch) ----------
__global__ void __launch_bounds__(256) wprep(const float* __restrict__ cnn,
                                             const float* __restrict__ gaz,
                                             const float* __restrict__ gazb,
                                             const float* __restrict__ gm,
                                             const float* __restrict__ expi,
                                             const float* __restrict__ Wcat,
                                             const float* __restrict__ Wexp)
{
    if (blockIdx.x < 32768) {
        // activations -> g_ah [r][k]
        int idx = blockIdx.x * 256 + threadIdx.x;
        int k4  = idx & 127;
        int r   = idx >> 7;
        int j = r >> 14, b = (r >> 9) & 31, s = r & 511;
        int k = k4 * 4;
        int sel = k >> 7;
        const float* rp;
        if (sel == 0)      rp = cnn  + ((size_t)(b * 2048 + j * 512 + s) << 7);
        else if (sel == 1) rp = ((j & 1) ? gazb : gaz) + ((size_t)(b * 512 + s) << 7);
        else if (sel == 2) rp = gm   + ((size_t)(b * 512 + s) << 7);
        else               rp = expi + ((size_t)(b * 512 + s) << 7);
        float4 v = *reinterpret_cast<const float4*>(rp + (k & 127));
        __half2 h0 = __floats2half2_rn(v.x, v.y);
        __half2 h1 = __floats2half2_rn(v.z, v.w);
        *reinterpret_cast<uint2*>(g_ah + (size_t)r * 1024 + k4 * 8) =
            make_uint2(*reinterpret_cast<uint32_t*>(&h0), *reinterpret_cast<uint32_t*>(&h1));
    } else {
        // weights -> g_wh, columns reordered n' = h*4+g
        int idx = (blockIdx.x - 32768) * 256 + threadIdx.x;
        int h = idx & 127;
        int k = (idx >> 7) & 511;
        int j = idx >> 16;
#pragma unroll
        for (int g = 0; g < 4; g++) {
            float v;
            if (k < 384)     v = Wcat[(size_t)k * 2048 + j * 512 + g * 128 + h];
            else if (g >= 1) v = Wexp[(size_t)(k - 384) * 1536 + j * 384 + (g - 1) * 128 + h];
            else             v = 0.f;
            int npr = h * 4 + g;
            *reinterpret_cast<__half*>(g_wh + ((size_t)(j * 512) + npr) * 1024 + k * 2) =
                __float2half_rn(v);
        }
    }
}

// ---------- Main: 3-stage pipelined fp16 HMMA GEMM + fused epilogue ----------
__global__ void __launch_bounds__(256, 2)
layergate_mma(const float* __restrict__ cnn,
              const float* __restrict__ expi,
              const float* __restrict__ bcat,
              const float* __restrict__ bexp,
              float* __restrict__ out)
{
    extern __shared__ __align__(1024) unsigned char smem[];
    const uint32_t sbase = smem_u32(smem);
    const int tid  = threadIdx.x;
    const int lane = tid & 31;
    const int wid  = tid >> 5;
    const int wm   = wid & 3;     // 4 warps in M
    const int wn   = wid >> 2;    // 2 warps in N
    const int nt   = blockIdx.x;  // 0..3   (h-block of 32) — fastest => A rows L2-shared
    const int mx   = blockIdx.y;  // 0..127 (row tile within j)
    const int j    = blockIdx.z;  // 0..3
    const int rbase = j * 16384 + mx * 128;

    float acc[2][8][4];
#pragma unroll
    for (int mf = 0; mf < 2; mf++)
#pragma unroll
        for (int nf = 0; nf < 8; nf++)
#pragma unroll
            for (int c = 0; c < 4; c++) acc[mf][nf][c] = 0.f;

    // ---- cp.async stage loader: 8 x 16B per thread (A 16KB + B 16KB), K-slice = 64
    auto issue_stage = [&](int s) {
        const int buf = s % NSTAGE;
        const uint32_t dstStage = sbase + buf * STAGE_BYTES;
#pragma unroll
        for (int i = 0; i < 4; i++) {
            int c = i * 256 + tid;                 // 1024 A chunks
            int r = c >> 3, ch = c & 7;
            const unsigned char* src =
                g_ah + (size_t)(rbase + r) * 1024 + s * 128 + ch * 16;
            cp16(dstStage + r * 128 + ((ch ^ (r & 7)) * 16), src);
        }
#pragma unroll
        for (int i = 0; i < 4; i++) {
            int c = i * 256 + tid;                 // 1024 B chunks
            int r = c >> 3, ch = c & 7;
            const unsigned char* src =
                g_wh + ((size_t)(j * 512) + nt * 128 + r) * 1024 + s * 128 + ch * 16;
            cp16(dstStage + 16384 + r * 128 + ((ch ^ (r & 7)) * 16), src);
        }
        cp_commit();
    };

    // ldmatrix lane geometry
    const int arow = lane & 15;
    const int ac   = lane >> 4;
    const int brow = (lane & 7) | ((lane >> 4) << 3);
    const int bc   = (lane >> 3) & 1;

    auto compute_stage = [&](int s) {
        const int buf = s % NSTAGE;
        const uint32_t st = sbase + buf * STAGE_BYTES;
        const uint32_t aBase = st + (wm * 32 + arow) * 128;
        const uint32_t bBase = st + 16384 + (wn * 64 + brow) * 128;
#pragma unroll
        for (int kk = 0; kk < 4; kk++) {
            const uint32_t aoff = ((kk * 2 + ac) ^ (arow & 7)) * 16;
            const uint32_t boff = ((kk * 2 + bc) ^ (brow & 7)) * 16;
            uint32_t A[2][4];
#pragma unroll
            for (int mf = 0; mf < 2; mf++) ldsm4(A[mf], aBase + mf * 2048 + aoff);
            uint32_t B[8][2];
#pragma unroll
            for (int ng = 0; ng < 4; ng++) {
                uint32_t t[4];
                ldsm4(t, bBase + ng * 2048 + boff);
                B[2 * ng][0] = t[0]; B[2 * ng][1] = t[1];
                B[2 * ng + 1][0] = t[2]; B[2 * ng + 1][1] = t[3];
            }
#pragma unroll
            for (int mf = 0; mf < 2; mf++)
#pragma unroll
                for (int nf = 0; nf < 8; nf++)
                    mma_fp16(acc[mf][nf], A[mf], B[nf]);
        }
    };

    issue_stage(0);
    issue_stage(1);
    for (int s = 0; s < 8; s++) {
        cp_wait1();                      // stage s landed (stage s+1 may still fly)
        __syncthreads();                 // all warps past compute(s-1); buf (s+2)%3 free
        if (s + 2 < 8) issue_stage(s + 2);
        else           cp_commit();      // empty group keeps wait arithmetic exact
        compute_stage(s);
    }

    // ---- Epilogue phase 1: dump acc to smem gate tile [128 rows][128 n'] fp32
    __syncthreads();
    float* gate = reinterpret_cast<float*>(smem);
    const int gid = lane >> 2, tig = lane & 3;
#pragma unroll
    for (int mf = 0; mf < 2; mf++)
#pragma unroll
        for (int nf = 0; nf < 8; nf++) {
            int row = wm * 32 + mf * 16 + gid;
            int col = wn * 64 + nf * 8 + tig * 2;
            *reinterpret_cast<float2*>(gate + row * 128 + col) =
                make_float2(acc[mf][nf][0], acc[mf][nf][1]);
            *reinterpret_cast<float2*>(gate + (row + 8) * 128 + col) =
                make_float2(acc[mf][nf][2], acc[mf][nf][3]);
        }
    __syncthreads();

    // ---- Epilogue phase 2: per (row, h) gather float4 {ns,g1,g2,g3}, finish, store
    const int hl = lane;
    const int hg = nt * 32 + hl;
    const float bc0 = bcat[j * 512 + hg];
    const float bc1 = bcat[j * 512 + 128 + hg];
    const float bc2 = bcat[j * 512 + 256 + hg];
    const float bc3 = bcat[j * 512 + 384 + hg];
    const float be1 = bexp[j * 384 + hg];
    const float be2 = bexp[j * 384 + 128 + hg];
    const float be3 = bexp[j * 384 + 256 + hg];
#pragma unroll
    for (int i = 0; i < 16; i++) {
        const int row = wid * 16 + i;
        const int r = rbase + row;
        const int bb = (r >> 9) & 31, ss = r & 511;
        float4 gv = *reinterpret_cast<const float4*>(gate + row * 128 + hl * 4);
        float s1 = cnn[((size_t)(bb * 2048 + j * 512 + ss) << 7) + hg];
        float s2 = expi[((size_t)(bb * 512 + ss) << 7) + hg];
        float ns = tanhf(gv.x + bc0);
        float g1 = 1.f / (1.f + __expf(-(gv.y + bc1 + be1)));
        float g2 = 1.f / (1.f + __expf(-(gv.z + bc2 + be2)));
        float g3 = 1.f / (1.f + __expf(-(gv.w + bc3 + be3)));
        float e1 = __expf(g1), e2 = __expf(g2), e3 = __expf(g3);
        float inv = 1.f / (e1 + e2 + e3);
        out[((size_t)r << 7) + hg] = (e1 * ns + e2 * s1 + e3 * s2) * inv;
    }
}

extern "C" void kernel_launch(void* const* d_in, const int* in_sizes, int n_in,
                              void* d_out, int out_size)
{
    const float* cnn  = (const float*)d_in[0];
    const float* gaz  = (const float*)d_in[1];
    const float* gazb = (const float*)d_in[2];
    const float* gm   = (const float*)d_in[3];
    const float* expi = (const float*)d_in[4];
    const float* Wcat = (const float*)d_in[5];
    const float* bcat = (const float*)d_in[6];
    const float* Wexp = (const float*)d_in[7];
    const float* bexp = (const float*)d_in[8];
    float* out = (float*)d_out;

    wprep<<<33792, 256>>>(cnn, gaz, gazb, gm, expi, Wcat, Wexp);

    cudaFuncSetAttribute(layergate_mma,
                         cudaFuncAttributeMaxDynamicSharedMemorySize, SMEM_TOTAL);
    layergate_mma<<<dim3(4, 128, 4), 256, SMEM_TOTAL>>>(cnn, expi, bcat, bexp, out);
}